// round 1
// baseline (speedup 1.0000x reference)
#include <cuda_runtime.h>
#include <cuda_bf16.h>
#include <cstdint>

// Problem constants
#define HDIM 1024
#define BDIM 2048
#define SDIM 64
#define MROWS (BDIM * SDIM)   // 131072

// ---------------- scratch (static __device__ arrays; no allocation) ----------------
__device__ __nv_bfloat16 g_kc[(size_t)MROWS * HDIM];     // 256 MiB: prev_out_M @ Wk (pre-bias, pre-LN) in bf16
__device__ __nv_bfloat16 g_qpre[(size_t)BDIM * HDIM];    // 4 MiB:  in_val @ Wq
__device__ float         g_q[(size_t)BDIM * HDIM];       // 8 MiB:  LayerNormed query
__device__ float         g_beta[(size_t)BDIM * SDIM];    // 0.5 MiB

// ---------------- bf16 mma.sync GEMM:  C[M,1024] = A[M,1024] @ W[1024,1024] ----------------
// CTA tile 128x128, 8 warps (2x4), warp tile 64x32, k-chunk 32.
// A,W are fp32 in gmem; converted to bf16 on the gmem->smem path. C stored bf16.
__global__ __launch_bounds__(256) void gemm_bf16_k(
    const float* __restrict__ A, const float* __restrict__ W,
    __nv_bfloat16* __restrict__ C)
{
    __shared__ __nv_bfloat16 As[128][34];   // row-major, k contiguous (+pad)
    __shared__ __nv_bfloat16 Bs[128][34];   // n-major rows, k contiguous (+pad)

    const int tid   = threadIdx.x;
    const int lane  = tid & 31;
    const int wid   = tid >> 5;
    const int warpM = wid >> 2;      // 0..1
    const int warpN = wid & 3;       // 0..3
    const size_t bm = (size_t)blockIdx.y * 128;
    const int    bn = blockIdx.x * 128;

    float acc[4][4][4];
    #pragma unroll
    for (int mt = 0; mt < 4; mt++)
        #pragma unroll
        for (int nt = 0; nt < 4; nt++)
            #pragma unroll
            for (int i = 0; i < 4; i++) acc[mt][nt][i] = 0.f;

    const int ar  = tid >> 1;          // 0..127
    const int acb = (tid & 1) * 16;    // 0 or 16
    const int bkr = tid >> 3;          // 0..31
    const int bnb = (tid & 7) * 16;    // 0..112

    for (int k0 = 0; k0 < HDIM; k0 += 32) {
        // A tile: 128 rows x 32 k (fp32 -> bf16)
        {
            const float4* src = (const float4*)(A + (bm + ar) * HDIM + k0 + acb);
            #pragma unroll
            for (int i = 0; i < 4; i++) {
                float4 v = src[i];
                As[ar][acb + 4*i + 0] = __float2bfloat16(v.x);
                As[ar][acb + 4*i + 1] = __float2bfloat16(v.y);
                As[ar][acb + 4*i + 2] = __float2bfloat16(v.z);
                As[ar][acb + 4*i + 3] = __float2bfloat16(v.w);
            }
        }
        // W tile: rows k0..k0+31 (k), cols bn..bn+127 (n); stored transposed (n-major)
        {
            const float4* src = (const float4*)(W + (size_t)(k0 + bkr) * HDIM + bn + bnb);
            #pragma unroll
            for (int i = 0; i < 4; i++) {
                float4 v = src[i];
                Bs[bnb + 4*i + 0][bkr] = __float2bfloat16(v.x);
                Bs[bnb + 4*i + 1][bkr] = __float2bfloat16(v.y);
                Bs[bnb + 4*i + 2][bkr] = __float2bfloat16(v.z);
                Bs[bnb + 4*i + 3][bkr] = __float2bfloat16(v.w);
            }
        }
        __syncthreads();

        #pragma unroll
        for (int ks = 0; ks < 32; ks += 16) {
            uint32_t af[4][4];
            uint32_t bfr[4][2];
            #pragma unroll
            for (int mt = 0; mt < 4; mt++) {
                int r = warpM * 64 + mt * 16 + (lane >> 2);
                int c = ks + (lane & 3) * 2;
                af[mt][0] = *(const uint32_t*)&As[r    ][c    ];
                af[mt][1] = *(const uint32_t*)&As[r + 8][c    ];
                af[mt][2] = *(const uint32_t*)&As[r    ][c + 8];
                af[mt][3] = *(const uint32_t*)&As[r + 8][c + 8];
            }
            #pragma unroll
            for (int nt = 0; nt < 4; nt++) {
                int n = warpN * 32 + nt * 8 + (lane >> 2);
                int c = ks + (lane & 3) * 2;
                bfr[nt][0] = *(const uint32_t*)&Bs[n][c    ];
                bfr[nt][1] = *(const uint32_t*)&Bs[n][c + 8];
            }
            #pragma unroll
            for (int mt = 0; mt < 4; mt++)
                #pragma unroll
                for (int nt = 0; nt < 4; nt++)
                    asm volatile(
                        "mma.sync.aligned.m16n8k16.row.col.f32.bf16.bf16.f32 "
                        "{%0,%1,%2,%3},{%4,%5,%6,%7},{%8,%9},{%0,%1,%2,%3};\n"
                        : "+f"(acc[mt][nt][0]), "+f"(acc[mt][nt][1]),
                          "+f"(acc[mt][nt][2]), "+f"(acc[mt][nt][3])
                        : "r"(af[mt][0]), "r"(af[mt][1]), "r"(af[mt][2]), "r"(af[mt][3]),
                          "r"(bfr[nt][0]), "r"(bfr[nt][1]));
        }
        __syncthreads();
    }

    // Epilogue: store bf16
    #pragma unroll
    for (int mt = 0; mt < 4; mt++) {
        int r = warpM * 64 + mt * 16 + (lane >> 2);
        #pragma unroll
        for (int nt = 0; nt < 4; nt++) {
            int c = bn + warpN * 32 + nt * 8 + (lane & 3) * 2;
            size_t b0 = (bm + r) * HDIM + c;
            *(__nv_bfloat162*)(C + b0) =
                __floats2bfloat162_rn(acc[mt][nt][0], acc[mt][nt][1]);
            *(__nv_bfloat162*)(C + b0 + (size_t)8 * HDIM) =
                __floats2bfloat162_rn(acc[mt][nt][2], acc[mt][nt][3]);
        }
    }
}

// ---------------- LayerNorm for query: q = LN(qpre + bq)*gq + betaq ----------------
// One warp per row; 8 warps per CTA.
__global__ __launch_bounds__(256) void ln_q_k(
    const __nv_bfloat16* __restrict__ qpre,
    const float* __restrict__ bq, const float* __restrict__ gq,
    const float* __restrict__ betaq, float* __restrict__ qout)
{
    const int lane = threadIdx.x & 31;
    const int wid  = threadIdx.x >> 5;
    const int row  = blockIdx.x * 8 + wid;
    const size_t base = (size_t)row * HDIM;

    float x[32];
    float s = 0.f, sq = 0.f;
    #pragma unroll
    for (int i = 0; i < 32; i++) {
        int j = i * 32 + lane;
        x[i] = __bfloat162float(qpre[base + j]) + bq[j];
        s  += x[i];
        sq += x[i] * x[i];
    }
    #pragma unroll
    for (int o = 16; o > 0; o >>= 1) {
        s  += __shfl_xor_sync(0xffffffffu, s,  o);
        sq += __shfl_xor_sync(0xffffffffu, sq, o);
    }
    float mean = s * (1.f / 1024.f);
    float var  = sq * (1.f / 1024.f) - mean * mean;
    float rstd = rsqrtf(var + 1e-5f);
    #pragma unroll
    for (int i = 0; i < 32; i++) {
        int j = i * 32 + lane;
        qout[base + j] = (x[i] - mean) * rstd * gq[j] + betaq[j];
    }
}

// ---------------- fused: keyp-LN + relu(q+keyp) . Wb -> beta ----------------
// One CTA per batch b (512 thr = 16 warps, each warp handles rows s=w, w+16, ...)
__global__ __launch_bounds__(512) void beta_k(
    const __nv_bfloat16* __restrict__ kc, const float* __restrict__ q,
    const float* __restrict__ bk, const float* __restrict__ gk,
    const float* __restrict__ betak, const float* __restrict__ Wb,
    const float* __restrict__ bb, float* __restrict__ beta)
{
    __shared__ float qs[HDIM], wbs[HDIM], bks[HDIM], gks[HDIM], bes[HDIM];
    const int b    = blockIdx.x;
    const int tid  = threadIdx.x;
    const int lane = tid & 31;
    const int wid  = tid >> 5;

    for (int j = tid; j < HDIM; j += 512) {
        qs[j]  = q[(size_t)b * HDIM + j];
        wbs[j] = Wb[j];
        bks[j] = bk[j];
        gks[j] = gk[j];
        bes[j] = betak[j];
    }
    __syncthreads();
    const float bbv = bb[0];

    for (int s = wid; s < SDIM; s += 16) {
        const size_t base = ((size_t)b * SDIM + s) * HDIM;
        float x[32];
        float sm = 0.f, sq = 0.f;
        #pragma unroll
        for (int i = 0; i < 32; i++) {
            int j = i * 32 + lane;
            x[i] = __bfloat162float(kc[base + j]) + bks[j];
            sm += x[i];
            sq += x[i] * x[i];
        }
        #pragma unroll
        for (int o = 16; o > 0; o >>= 1) {
            sm += __shfl_xor_sync(0xffffffffu, sm, o);
            sq += __shfl_xor_sync(0xffffffffu, sq, o);
        }
        float mean = sm * (1.f / 1024.f);
        float var  = sq * (1.f / 1024.f) - mean * mean;
        float rstd = rsqrtf(var + 1e-5f);

        float acc = 0.f;
        #pragma unroll
        for (int i = 0; i < 32; i++) {
            int j  = i * 32 + lane;
            float kv = (x[i] - mean) * rstd * gks[j] + bes[j];
            float hv = qs[j] + kv;
            acc += fmaxf(hv, 0.f) * wbs[j];
        }
        #pragma unroll
        for (int o = 16; o > 0; o >>= 1)
            acc += __shfl_xor_sync(0xffffffffu, acc, o);

        if (lane == 0)
            beta[(size_t)b * SDIM + s] = (acc + bbv) * (1.f / 32.f);
    }
}

// ---------------- masked softmax + cumsums -> (cp, rcp, p) ----------------
// One thread per batch row b; S=64 handled sequentially (tiny kernel).
__global__ void softmax_k(const float* __restrict__ beta,
                          const float* __restrict__ prev_p,
                          float* __restrict__ out)
{
    int b = blockIdx.x * blockDim.x + threadIdx.x;
    if (b >= BDIM) return;
    const float* bt = beta   + (size_t)b * SDIM;
    const float* pp = prev_p + (size_t)b * SDIM;

    float mx = -1e30f;
    #pragma unroll
    for (int s = 0; s < SDIM; s++) mx = fmaxf(mx, bt[s]);

    float pcs[SDIM];
    float run = 0.f;
    #pragma unroll
    for (int s = 0; s < SDIM; s++) { run += pp[s]; pcs[s] = run; }

    float x[SDIM];
    float denom = 0.f;
    #pragma unroll
    for (int s = 0; s < SDIM; s++) {
        float mask = (s < SDIM - 1)
                   ? ((pcs[s + 1] < 1e-5f) ? 0.f : pcs[s + 1])
                   : 1.f;
        x[s] = expf(bt[s] - mx) * mask;
        denom += fabsf(x[s]);
    }
    denom = fmaxf(denom, 1e-12f);

    const size_t BS = (size_t)BDIM * SDIM;
    float cp = 0.f;
    #pragma unroll
    for (int s = 0; s < SDIM; s++) {
        float p = x[s] / denom;
        x[s] = p;
        cp += p;
        out[0 * BS + (size_t)b * SDIM + s] = cp;   // cp
        out[2 * BS + (size_t)b * SDIM + s] = p;    // p
    }
    float rcp = 0.f;
    #pragma unroll
    for (int s = SDIM - 1; s >= 0; s--) {
        rcp += x[s];
        out[1 * BS + (size_t)b * SDIM + s] = rcp;  // rcp
    }
}

// ---------------- launch ----------------
extern "C" void kernel_launch(void* const* d_in, const int* in_sizes, int n_in,
                              void* d_out, int out_size)
{
    const float* in_val     = (const float*)d_in[0];
    const float* prev_out_M = (const float*)d_in[1];
    const float* prev_p     = (const float*)d_in[2];
    const float* Wq         = (const float*)d_in[3];
    const float* bq         = (const float*)d_in[4];
    const float* gq         = (const float*)d_in[5];
    const float* betaq      = (const float*)d_in[6];
    const float* Wk         = (const float*)d_in[7];
    const float* bk         = (const float*)d_in[8];
    const float* gk         = (const float*)d_in[9];
    const float* betak      = (const float*)d_in[10];
    const float* Wb         = (const float*)d_in[11];
    const float* bb         = (const float*)d_in[12];
    float* out = (float*)d_out;

    __nv_bfloat16 *kc, *qpre;
    float *qf, *betap;
    cudaGetSymbolAddress((void**)&kc,    g_kc);
    cudaGetSymbolAddress((void**)&qpre,  g_qpre);
    cudaGetSymbolAddress((void**)&qf,    g_q);
    cudaGetSymbolAddress((void**)&betap, g_beta);

    // query pre-LN: [2048,1024] @ [1024,1024]
    gemm_bf16_k<<<dim3(8, BDIM / 128), 256>>>(in_val, Wq, qpre);
    // keyp pre-LN: [131072,1024] @ [1024,1024]  (dominant GEMM)
    gemm_bf16_k<<<dim3(8, MROWS / 128), 256>>>(prev_out_M, Wk, kc);
    // LN(query)
    ln_q_k<<<BDIM / 8, 256>>>(qpre, bq, gq, betaq, qf);
    // LN(keyp) + relu(q+keyp).Wb -> beta
    beta_k<<<BDIM, 512>>>(kc, qf, bk, gk, betak, Wb, bb, betap);
    // masked softmax + scans -> out = [cp | rcp | p]
    softmax_k<<<(BDIM + 127) / 128, 128>>>(betap, prev_p, out);
}

// round 2
// speedup vs baseline: 2.0126x; 2.0126x over previous
#include <cuda_runtime.h>
#include <cuda_bf16.h>
#include <cstdint>

#define HDIM 1024
#define BDIM 2048
#define SDIM 64
#define MROWS (BDIM * SDIM)   // 131072
#define KT    (HDIM / 32)     // 32 k-chunks

// ---------------- scratch (static __device__ arrays; no allocation) ----------------
__device__ __nv_bfloat16 g_abf [(size_t)MROWS * HDIM];   // 256 MiB: prev_out_M in bf16
__device__ __nv_bfloat16 g_inbf[(size_t)BDIM * HDIM];    // 4 MiB:  in_val in bf16
__device__ __nv_bfloat16 g_wqt [(size_t)HDIM * HDIM];    // 2 MiB:  Wq^T bf16 (n-major)
__device__ __nv_bfloat16 g_wkt [(size_t)HDIM * HDIM];    // 2 MiB:  Wk^T bf16
__device__ __nv_bfloat16 g_kc  [(size_t)MROWS * HDIM];   // 256 MiB: prev_out_M @ Wk (pre-bias/LN)
__device__ __nv_bfloat16 g_qpre[(size_t)BDIM * HDIM];    // 4 MiB:  in_val @ Wq
__device__ float         g_q   [(size_t)BDIM * HDIM];    // 8 MiB:  LN(query)
__device__ float         g_beta[(size_t)BDIM * SDIM];    // 0.5 MiB

#define CP16(sm, gm) \
    asm volatile("cp.async.cg.shared.global [%0], [%1], 16;\n" :: "r"(sm), "l"(gm))

// ---------------- fp32 -> bf16 elementwise convert (8 elems/thread) ----------------
__global__ __launch_bounds__(256) void cvt_k(const float* __restrict__ in,
                                             __nv_bfloat16* __restrict__ out)
{
    size_t i = ((size_t)blockIdx.x * blockDim.x + threadIdx.x) * 8;
    float4 a = *(const float4*)(in + i);
    float4 b = *(const float4*)(in + i + 4);
    __nv_bfloat162 r[4];
    r[0] = __floats2bfloat162_rn(a.x, a.y);
    r[1] = __floats2bfloat162_rn(a.z, a.w);
    r[2] = __floats2bfloat162_rn(b.x, b.y);
    r[3] = __floats2bfloat162_rn(b.z, b.w);
    *(uint4*)(out + i) = *(const uint4*)r;
}

// ---------------- transpose + convert: Wt[n][k] = bf16(W[k][n]) ----------------
__global__ __launch_bounds__(256) void cvtT_k(const float* __restrict__ W,
                                              __nv_bfloat16* __restrict__ Wt)
{
    __shared__ float t[32][33];
    int x  = blockIdx.x * 32 + threadIdx.x;   // source col (n)
    int y0 = blockIdx.y * 32;                 // source row (k)
    #pragma unroll
    for (int r = threadIdx.y; r < 32; r += 8)
        t[r][threadIdx.x] = W[(size_t)(y0 + r) * HDIM + x];
    __syncthreads();
    int xo = y0 + threadIdx.x;                // dest col (k)
    #pragma unroll
    for (int r = threadIdx.y; r < 32; r += 8)
        Wt[(size_t)(blockIdx.x * 32 + r) * HDIM + xo] = __float2bfloat16(t[threadIdx.x][r]);
}

// ---------------- pipelined bf16 GEMM:  C[M,1024] = A[M,1024] @ Bt^T ----------------
// A row-major bf16, Bt n-major bf16 (Bt[n][k] = W[k][n]). CTA tile 128x128, k-chunk 32,
// 2-stage cp.async double buffer. 8 warps (2x4), warp tile 64x32.
// smem rows padded to 40 elems (80B): 16B-aligned for cp.async, conflict-free LDS.
__global__ __launch_bounds__(256) void gemm_bf16_k(
    const __nv_bfloat16* __restrict__ A, const __nv_bfloat16* __restrict__ Bt,
    __nv_bfloat16* __restrict__ C)
{
    __shared__ __nv_bfloat16 As[2][128][40];
    __shared__ __nv_bfloat16 Bs[2][128][40];

    const int tid   = threadIdx.x;
    const int lane  = tid & 31;
    const int wid   = tid >> 5;
    const int warpM = wid >> 2;      // 0..1
    const int warpN = wid & 3;       // 0..3
    const size_t bm = (size_t)blockIdx.y * 128;
    const size_t bn = (size_t)blockIdx.x * 128;

    float acc[4][4][4];
    #pragma unroll
    for (int mt = 0; mt < 4; mt++)
        #pragma unroll
        for (int nt = 0; nt < 4; nt++)
            #pragma unroll
            for (int i = 0; i < 4; i++) acc[mt][nt][i] = 0.f;

    // cp.async mapping: thread copies 32B (2x16B) of one row per tile
    const int crow = tid >> 1;        // 0..127
    const int cel  = (tid & 1) * 16;  // element offset 0 or 16

    const __nv_bfloat16* gA = A  + (bm + crow) * HDIM + cel;
    const __nv_bfloat16* gB = Bt + (bn + crow) * HDIM + cel;
    uint32_t sA0 = (uint32_t)__cvta_generic_to_shared(&As[0][crow][cel]);
    uint32_t sB0 = (uint32_t)__cvta_generic_to_shared(&Bs[0][crow][cel]);
    const uint32_t stageA = (uint32_t)((char*)&As[1][0][0] - (char*)&As[0][0][0]);
    const uint32_t stageB = (uint32_t)((char*)&Bs[1][0][0] - (char*)&Bs[0][0][0]);

    // prologue: stage 0
    CP16(sA0,      gA);     CP16(sA0 + 16, gA + 8);
    CP16(sB0,      gB);     CP16(sB0 + 16, gB + 8);
    asm volatile("cp.async.commit_group;\n");

    for (int kt = 0; kt < KT; kt++) {
        if (kt + 1 < KT) {
            int buf = (kt + 1) & 1;
            const __nv_bfloat16* ga = gA + (kt + 1) * 32;
            const __nv_bfloat16* gb = gB + (kt + 1) * 32;
            uint32_t sa = sA0 + buf * stageA;
            uint32_t sb = sB0 + buf * stageB;
            CP16(sa,      ga);     CP16(sa + 16, ga + 8);
            CP16(sb,      gb);     CP16(sb + 16, gb + 8);
            asm volatile("cp.async.commit_group;\n");
            asm volatile("cp.async.wait_group 1;\n");
        } else {
            asm volatile("cp.async.wait_group 0;\n");
        }
        __syncthreads();

        const int buf = kt & 1;
        #pragma unroll
        for (int ks = 0; ks < 32; ks += 16) {
            uint32_t af[4][4];
            uint32_t bfr[4][2];
            #pragma unroll
            for (int mt = 0; mt < 4; mt++) {
                int r = warpM * 64 + mt * 16 + (lane >> 2);
                int c = ks + (lane & 3) * 2;
                af[mt][0] = *(const uint32_t*)&As[buf][r    ][c    ];
                af[mt][1] = *(const uint32_t*)&As[buf][r + 8][c    ];
                af[mt][2] = *(const uint32_t*)&As[buf][r    ][c + 8];
                af[mt][3] = *(const uint32_t*)&As[buf][r + 8][c + 8];
            }
            #pragma unroll
            for (int nt = 0; nt < 4; nt++) {
                int n = warpN * 32 + nt * 8 + (lane >> 2);
                int c = ks + (lane & 3) * 2;
                bfr[nt][0] = *(const uint32_t*)&Bs[buf][n][c    ];
                bfr[nt][1] = *(const uint32_t*)&Bs[buf][n][c + 8];
            }
            #pragma unroll
            for (int mt = 0; mt < 4; mt++)
                #pragma unroll
                for (int nt = 0; nt < 4; nt++)
                    asm volatile(
                        "mma.sync.aligned.m16n8k16.row.col.f32.bf16.bf16.f32 "
                        "{%0,%1,%2,%3},{%4,%5,%6,%7},{%8,%9},{%0,%1,%2,%3};\n"
                        : "+f"(acc[mt][nt][0]), "+f"(acc[mt][nt][1]),
                          "+f"(acc[mt][nt][2]), "+f"(acc[mt][nt][3])
                        : "r"(af[mt][0]), "r"(af[mt][1]), "r"(af[mt][2]), "r"(af[mt][3]),
                          "r"(bfr[nt][0]), "r"(bfr[nt][1]));
        }
        __syncthreads();
    }

    #pragma unroll
    for (int mt = 0; mt < 4; mt++) {
        int r = warpM * 64 + mt * 16 + (lane >> 2);
        #pragma unroll
        for (int nt = 0; nt < 4; nt++) {
            size_t c  = bn + warpN * 32 + nt * 8 + (lane & 3) * 2;
            size_t b0 = (bm + r) * HDIM + c;
            *(__nv_bfloat162*)(C + b0) =
                __floats2bfloat162_rn(acc[mt][nt][0], acc[mt][nt][1]);
            *(__nv_bfloat162*)(C + b0 + (size_t)8 * HDIM) =
                __floats2bfloat162_rn(acc[mt][nt][2], acc[mt][nt][3]);
        }
    }
}

// ---------------- LayerNorm for query ----------------
__global__ __launch_bounds__(256) void ln_q_k(
    const __nv_bfloat16* __restrict__ qpre,
    const float* __restrict__ bq, const float* __restrict__ gq,
    const float* __restrict__ betaq, float* __restrict__ qout)
{
    const int lane = threadIdx.x & 31;
    const int wid  = threadIdx.x >> 5;
    const int row  = blockIdx.x * 8 + wid;
    const size_t base = (size_t)row * HDIM;

    float x[32];
    float s = 0.f, sq = 0.f;
    #pragma unroll
    for (int i = 0; i < 16; i++) {
        int j = i * 64 + lane * 2;
        __nv_bfloat162 v = *(const __nv_bfloat162*)(qpre + base + j);
        float a = __low2float(v)  + bq[j];
        float c = __high2float(v) + bq[j + 1];
        x[2*i] = a; x[2*i+1] = c;
        s += a + c; sq += a * a + c * c;
    }
    #pragma unroll
    for (int o = 16; o > 0; o >>= 1) {
        s  += __shfl_xor_sync(0xffffffffu, s,  o);
        sq += __shfl_xor_sync(0xffffffffu, sq, o);
    }
    float mean = s * (1.f / 1024.f);
    float var  = sq * (1.f / 1024.f) - mean * mean;
    float rstd = rsqrtf(var + 1e-5f);
    #pragma unroll
    for (int i = 0; i < 16; i++) {
        int j = i * 64 + lane * 2;
        float2 o;
        o.x = (x[2*i]   - mean) * rstd * gq[j]   + betaq[j];
        o.y = (x[2*i+1] - mean) * rstd * gq[j+1] + betaq[j+1];
        *(float2*)(qout + base + j) = o;
    }
}

// ---------------- fused: keyp-LN + relu(q+keyp) . Wb -> beta ----------------
// 256 threads (8 warps), 1 CTA per batch b, each warp does 8 rows.
__global__ __launch_bounds__(256) void beta_k(
    const __nv_bfloat16* __restrict__ kc, const float* __restrict__ q,
    const float* __restrict__ bk, const float* __restrict__ gk,
    const float* __restrict__ betak, const float* __restrict__ Wb,
    const float* __restrict__ bb, float* __restrict__ beta)
{
    __shared__ float qs[HDIM], wbs[HDIM], bks[HDIM], gks[HDIM], bes[HDIM];
    const int b    = blockIdx.x;
    const int tid  = threadIdx.x;
    const int lane = tid & 31;
    const int wid  = tid >> 5;

    for (int j = tid; j < HDIM; j += 256) {
        qs[j]  = q[(size_t)b * HDIM + j];
        wbs[j] = Wb[j];
        bks[j] = bk[j];
        gks[j] = gk[j];
        bes[j] = betak[j];
    }
    __syncthreads();
    const float bbv = bb[0];

    for (int s = wid; s < SDIM; s += 8) {
        const size_t base = ((size_t)b * SDIM + s) * HDIM;
        float x[32];
        float sm = 0.f, sq = 0.f;
        #pragma unroll
        for (int i = 0; i < 16; i++) {
            int j = i * 64 + lane * 2;
            __nv_bfloat162 v = *(const __nv_bfloat162*)(kc + base + j);
            float a = __low2float(v)  + bks[j];
            float c = __high2float(v) + bks[j + 1];
            x[2*i] = a; x[2*i+1] = c;
            sm += a + c; sq += a * a + c * c;
        }
        #pragma unroll
        for (int o = 16; o > 0; o >>= 1) {
            sm += __shfl_xor_sync(0xffffffffu, sm, o);
            sq += __shfl_xor_sync(0xffffffffu, sq, o);
        }
        float mean = sm * (1.f / 1024.f);
        float var  = sq * (1.f / 1024.f) - mean * mean;
        float rstd = rsqrtf(var + 1e-5f);

        float acc = 0.f;
        #pragma unroll
        for (int i = 0; i < 16; i++) {
            int j = i * 64 + lane * 2;
            float kv0 = (x[2*i]   - mean) * rstd * gks[j]   + bes[j];
            float kv1 = (x[2*i+1] - mean) * rstd * gks[j+1] + bes[j+1];
            acc += fmaxf(qs[j]   + kv0, 0.f) * wbs[j];
            acc += fmaxf(qs[j+1] + kv1, 0.f) * wbs[j+1];
        }
        #pragma unroll
        for (int o = 16; o > 0; o >>= 1)
            acc += __shfl_xor_sync(0xffffffffu, acc, o);

        if (lane == 0)
            beta[(size_t)b * SDIM + s] = (acc + bbv) * (1.f / 32.f);
    }
}

// ---------------- masked softmax + cumsums -> (cp, rcp, p) ----------------
__global__ void softmax_k(const float* __restrict__ beta,
                          const float* __restrict__ prev_p,
                          float* __restrict__ out)
{
    int b = blockIdx.x * blockDim.x + threadIdx.x;
    if (b >= BDIM) return;
    const float* bt = beta   + (size_t)b * SDIM;
    const float* pp = prev_p + (size_t)b * SDIM;

    float mx = -1e30f;
    #pragma unroll
    for (int s = 0; s < SDIM; s++) mx = fmaxf(mx, bt[s]);

    float pcs[SDIM];
    float run = 0.f;
    #pragma unroll
    for (int s = 0; s < SDIM; s++) { run += pp[s]; pcs[s] = run; }

    float x[SDIM];
    float denom = 0.f;
    #pragma unroll
    for (int s = 0; s < SDIM; s++) {
        float mask = (s < SDIM - 1)
                   ? ((pcs[s + 1] < 1e-5f) ? 0.f : pcs[s + 1])
                   : 1.f;
        x[s] = expf(bt[s] - mx) * mask;
        denom += fabsf(x[s]);
    }
    denom = fmaxf(denom, 1e-12f);

    const size_t BS = (size_t)BDIM * SDIM;
    float cp = 0.f;
    #pragma unroll
    for (int s = 0; s < SDIM; s++) {
        float p = x[s] / denom;
        x[s] = p;
        cp += p;
        out[0 * BS + (size_t)b * SDIM + s] = cp;
        out[2 * BS + (size_t)b * SDIM + s] = p;
    }
    float rcp = 0.f;
    #pragma unroll
    for (int s = SDIM - 1; s >= 0; s--) {
        rcp += x[s];
        out[1 * BS + (size_t)b * SDIM + s] = rcp;
    }
}

// ---------------- launch ----------------
extern "C" void kernel_launch(void* const* d_in, const int* in_sizes, int n_in,
                              void* d_out, int out_size)
{
    const float* in_val     = (const float*)d_in[0];
    const float* prev_out_M = (const float*)d_in[1];
    const float* prev_p     = (const float*)d_in[2];
    const float* Wq         = (const float*)d_in[3];
    const float* bq         = (const float*)d_in[4];
    const float* gq         = (const float*)d_in[5];
    const float* betaq      = (const float*)d_in[6];
    const float* Wk         = (const float*)d_in[7];
    const float* bk         = (const float*)d_in[8];
    const float* gk         = (const float*)d_in[9];
    const float* betak      = (const float*)d_in[10];
    const float* Wb         = (const float*)d_in[11];
    const float* bb         = (const float*)d_in[12];
    float* out = (float*)d_out;

    __nv_bfloat16 *abf, *inbf, *wqt, *wkt, *kc, *qpre;
    float *qf, *betap;
    cudaGetSymbolAddress((void**)&abf,   g_abf);
    cudaGetSymbolAddress((void**)&inbf,  g_inbf);
    cudaGetSymbolAddress((void**)&wqt,   g_wqt);
    cudaGetSymbolAddress((void**)&wkt,   g_wkt);
    cudaGetSymbolAddress((void**)&kc,    g_kc);
    cudaGetSymbolAddress((void**)&qpre,  g_qpre);
    cudaGetSymbolAddress((void**)&qf,    g_q);
    cudaGetSymbolAddress((void**)&betap, g_beta);

    // converts
    cvt_k <<<((size_t)MROWS * HDIM / 8) / 256, 256>>>(prev_out_M, abf);
    cvt_k <<<((size_t)BDIM  * HDIM / 8) / 256, 256>>>(in_val, inbf);
    cvtT_k<<<dim3(32, 32), dim3(32, 8)>>>(Wq, wqt);
    cvtT_k<<<dim3(32, 32), dim3(32, 8)>>>(Wk, wkt);

    // GEMMs
    gemm_bf16_k<<<dim3(8, BDIM  / 128), 256>>>(inbf, wqt, qpre);
    gemm_bf16_k<<<dim3(8, MROWS / 128), 256>>>(abf,  wkt, kc);

    // epilogue chain
    ln_q_k  <<<BDIM / 8, 256>>>(qpre, bq, gq, betaq, qf);
    beta_k  <<<BDIM, 256>>>(kc, qf, bk, gk, betak, Wb, bb, betap);
    softmax_k<<<(BDIM + 127) / 128, 128>>>(betap, prev_p, out);
}

// round 4
// speedup vs baseline: 2.6943x; 1.3387x over previous
#include <cuda_runtime.h>
#include <cuda_bf16.h>
#include <cstdint>

#define HDIM 1024
#define BDIM 2048
#define SDIM 64
#define MROWS (BDIM * SDIM)   // 131072

// ---------------- scratch ----------------
__device__ __nv_bfloat16 g_abf [(size_t)MROWS * HDIM];
__device__ __nv_bfloat16 g_inbf[(size_t)BDIM * HDIM];
__device__ __nv_bfloat16 g_wqt [(size_t)HDIM * HDIM];
__device__ __nv_bfloat16 g_wkt [(size_t)HDIM * HDIM];
__device__ __nv_bfloat16 g_kc  [(size_t)MROWS * HDIM];
__device__ __nv_bfloat16 g_qpre[(size_t)BDIM * HDIM];
__device__ float         g_q   [(size_t)BDIM * HDIM];
__device__ float         g_beta[(size_t)BDIM * SDIM];

#define CPASYNC16(sm, gm) \
    asm volatile("cp.async.cg.shared.global [%0], [%1], 16;\n" :: "r"(sm), "l"(gm))
#define CP_COMMIT() asm volatile("cp.async.commit_group;\n" ::: "memory")
#define CP_WAIT1()  asm volatile("cp.async.wait_group 1;\n" ::: "memory")
#define CP_WAIT0()  asm volatile("cp.async.wait_group 0;\n" ::: "memory")
#define LDMX4(r0, r1, r2, r3, a) \
    asm volatile("ldmatrix.sync.aligned.m8n8.x4.shared.b16 {%0,%1,%2,%3}, [%4];" \
        : "=r"(r0), "=r"(r1), "=r"(r2), "=r"(r3) : "r"(a))

__device__ __forceinline__ uint32_t smem_u32(const void* p) {
    uint32_t a;
    asm("{ .reg .u64 t; cvta.to.shared.u64 t, %1; cvt.u32.u64 %0, t; }" : "=r"(a) : "l"(p));
    return a;
}

// ================= pipelined bf16 mma.sync GEMM =================
// C[M,1024] = A[M,1024] @ Bt^T  (Bt n-major). CTA tile 128x128, k-chunk 64,
// 3-stage cp.async ring, 1 syncthreads/chunk, ldmatrix fragment loads,
// 2 CTAs/SM. 8 warps (2x4), warp tile 64x32.
#define NSTG   3
#define KC     64
#define CHUNKS (HDIM / KC)              // 16
#define RSTRIDE 144                     // 72 bf16 per row (64 + 8 pad)
#define STG_A   (128 * RSTRIDE)         // 18432 B
#define STG_BYTES (2 * STG_A)           // 36864 B (A + B)
#define GEMM_SMEM (NSTG * STG_BYTES)    // 110592 B

__global__ __launch_bounds__(256, 2) void gemm_bf16_k(
    const __nv_bfloat16* __restrict__ A, const __nv_bfloat16* __restrict__ Bt,
    __nv_bfloat16* __restrict__ C)
{
    extern __shared__ __align__(128) char smem[];
    const uint32_t sb = smem_u32(smem);

    const int tid   = threadIdx.x;
    const int lane  = tid & 31;
    const int wid   = tid >> 5;
    const int warpM = wid >> 2;      // 0..1
    const int warpN = wid & 3;       // 0..3
    const size_t bm = (size_t)blockIdx.y * 128;
    const size_t bn = (size_t)blockIdx.x * 128;

    float acc[4][4][4];
    #pragma unroll
    for (int mt = 0; mt < 4; mt++)
        #pragma unroll
        for (int nt = 0; nt < 4; nt++)
            #pragma unroll
            for (int i = 0; i < 4; i++) acc[mt][nt][i] = 0.f;

    // producer mapping: 256 threads x 4 iters x 16B per matrix
    const int prow = tid >> 3;          // 0..31 (+ i*32)
    const int pg   = tid & 7;           // 16B granule in row
    const __nv_bfloat16* gA = A  + (bm + prow) * HDIM + pg * 8;
    const __nv_bfloat16* gB = Bt + (bn + prow) * HDIM + pg * 8;
    const uint32_t pdst = prow * RSTRIDE + pg * 16;

    // ldmatrix base offsets (within a stage)
    const uint32_t aF = (warpM * 64 + ((lane >> 3) & 1) * 8 + (lane & 7)) * RSTRIDE
                      + ((lane >> 4) * 8) * 2;
    const uint32_t bF = STG_A
                      + (warpN * 32 + ((lane >> 4) & 1) * 8 + (lane & 7)) * RSTRIDE
                      + (((lane >> 3) & 1) * 8) * 2;

    // prologue: chunks 0,1
    #pragma unroll
    for (int kt = 0; kt < 2; kt++) {
        const uint32_t s = sb + kt * STG_BYTES;
        #pragma unroll
        for (int i = 0; i < 4; i++) {
            CPASYNC16(s + pdst + i * 32 * RSTRIDE,          gA + (size_t)i * 32 * HDIM + kt * KC);
            CPASYNC16(s + STG_A + pdst + i * 32 * RSTRIDE,  gB + (size_t)i * 32 * HDIM + kt * KC);
        }
        CP_COMMIT();
    }

    for (int kt = 0; kt < CHUNKS; kt++) {
        if (kt < CHUNKS - 1) CP_WAIT1(); else CP_WAIT0();
        __syncthreads();   // chunk kt visible to all; all warps done with buf (kt+2)%3

        // prefetch chunk kt+2 into buf (kt+2)%3
        if (kt + 2 < CHUNKS) {
            const uint32_t s = sb + ((kt + 2) % NSTG) * STG_BYTES;
            #pragma unroll
            for (int i = 0; i < 4; i++) {
                CPASYNC16(s + pdst + i * 32 * RSTRIDE,         gA + (size_t)i * 32 * HDIM + (kt + 2) * KC);
                CPASYNC16(s + STG_A + pdst + i * 32 * RSTRIDE, gB + (size_t)i * 32 * HDIM + (kt + 2) * KC);
            }
            CP_COMMIT();
        }

        const uint32_t stg = sb + (kt % NSTG) * STG_BYTES;
        #pragma unroll
        for (int ks = 0; ks < KC; ks += 16) {
            uint32_t af[4][4];
            uint32_t bf[4][2];
            #pragma unroll
            for (int mt = 0; mt < 4; mt++)
                LDMX4(af[mt][0], af[mt][1], af[mt][2], af[mt][3],
                      stg + aF + mt * 16 * RSTRIDE + ks * 2);
            #pragma unroll
            for (int np = 0; np < 2; np++) {
                uint32_t b0, b1, b2, b3;
                LDMX4(b0, b1, b2, b3, stg + bF + np * 16 * RSTRIDE + ks * 2);
                bf[2*np][0]   = b0; bf[2*np][1]   = b1;
                bf[2*np+1][0] = b2; bf[2*np+1][1] = b3;
            }
            #pragma unroll
            for (int mt = 0; mt < 4; mt++)
                #pragma unroll
                for (int nt = 0; nt < 4; nt++)
                    asm volatile(
                        "mma.sync.aligned.m16n8k16.row.col.f32.bf16.bf16.f32 "
                        "{%0,%1,%2,%3},{%4,%5,%6,%7},{%8,%9},{%0,%1,%2,%3};\n"
                        : "+f"(acc[mt][nt][0]), "+f"(acc[mt][nt][1]),
                          "+f"(acc[mt][nt][2]), "+f"(acc[mt][nt][3])
                        : "r"(af[mt][0]), "r"(af[mt][1]), "r"(af[mt][2]), "r"(af[mt][3]),
                          "r"(bf[nt][0]), "r"(bf[nt][1]));
        }
    }

    #pragma unroll
    for (int mt = 0; mt < 4; mt++) {
        int r = warpM * 64 + mt * 16 + (lane >> 2);
        #pragma unroll
        for (int nt = 0; nt < 4; nt++) {
            size_t c  = bn + warpN * 32 + nt * 8 + (lane & 3) * 2;
            size_t b0 = (bm + r) * HDIM + c;
            *(__nv_bfloat162*)(C + b0) =
                __floats2bfloat162_rn(acc[mt][nt][0], acc[mt][nt][1]);
            *(__nv_bfloat162*)(C + b0 + (size_t)8 * HDIM) =
                __floats2bfloat162_rn(acc[mt][nt][2], acc[mt][nt][3]);
        }
    }
}

// ---------------- fp32 -> bf16 convert ----------------
__global__ __launch_bounds__(256) void cvt_k(const float* __restrict__ in,
                                             __nv_bfloat16* __restrict__ out)
{
    size_t i = ((size_t)blockIdx.x * blockDim.x + threadIdx.x) * 8;
    float4 a = *(const float4*)(in + i);
    float4 b = *(const float4*)(in + i + 4);
    __nv_bfloat162 r[4];
    r[0] = __floats2bfloat162_rn(a.x, a.y);
    r[1] = __floats2bfloat162_rn(a.z, a.w);
    r[2] = __floats2bfloat162_rn(b.x, b.y);
    r[3] = __floats2bfloat162_rn(b.z, b.w);
    *(uint4*)(out + i) = *(const uint4*)r;
}

// ---------------- transpose + convert ----------------
__global__ __launch_bounds__(256) void cvtT_k(const float* __restrict__ W,
                                              __nv_bfloat16* __restrict__ Wt)
{
    __shared__ float t[32][33];
    int x  = blockIdx.x * 32 + threadIdx.x;
    int y0 = blockIdx.y * 32;
    #pragma unroll
    for (int r = threadIdx.y; r < 32; r += 8)
        t[r][threadIdx.x] = W[(size_t)(y0 + r) * HDIM + x];
    __syncthreads();
    int xo = y0 + threadIdx.x;
    #pragma unroll
    for (int r = threadIdx.y; r < 32; r += 8)
        Wt[(size_t)(blockIdx.x * 32 + r) * HDIM + xo] = __float2bfloat16(t[threadIdx.x][r]);
}

// ---------------- LayerNorm for query ----------------
__global__ __launch_bounds__(256) void ln_q_k(
    const __nv_bfloat16* __restrict__ qpre,
    const float* __restrict__ bq, const float* __restrict__ gq,
    const float* __restrict__ betaq, float* __restrict__ qout)
{
    const int lane = threadIdx.x & 31;
    const int wid  = threadIdx.x >> 5;
    const int row  = blockIdx.x * 8 + wid;
    const size_t base = (size_t)row * HDIM;

    float x[32];
    float s = 0.f, sq = 0.f;
    #pragma unroll
    for (int i = 0; i < 16; i++) {
        int j = i * 64 + lane * 2;
        __nv_bfloat162 v = *(const __nv_bfloat162*)(qpre + base + j);
        float a = __low2float(v)  + bq[j];
        float c = __high2float(v) + bq[j + 1];
        x[2*i] = a; x[2*i+1] = c;
        s += a + c; sq += a * a + c * c;
    }
    #pragma unroll
    for (int o = 16; o > 0; o >>= 1) {
        s  += __shfl_xor_sync(0xffffffffu, s,  o);
        sq += __shfl_xor_sync(0xffffffffu, sq, o);
    }
    float mean = s * (1.f / 1024.f);
    float var  = sq * (1.f / 1024.f) - mean * mean;
    float rstd = rsqrtf(var + 1e-5f);
    #pragma unroll
    for (int i = 0; i < 16; i++) {
        int j = i * 64 + lane * 2;
        float2 o;
        o.x = (x[2*i]   - mean) * rstd * gq[j]   + betaq[j];
        o.y = (x[2*i+1] - mean) * rstd * gq[j+1] + betaq[j+1];
        *(float2*)(qout + base + j) = o;
    }
}

// ---------------- fused: keyp-LN + relu(q+keyp) . Wb -> beta ----------------
__global__ __launch_bounds__(256) void beta_k(
    const __nv_bfloat16* __restrict__ kc, const float* __restrict__ q,
    const float* __restrict__ bk, const float* __restrict__ gk,
    const float* __restrict__ betak, const float* __restrict__ Wb,
    const float* __restrict__ bb, float* __restrict__ beta)
{
    __shared__ float qs[HDIM], wbs[HDIM], bks[HDIM], gks[HDIM], bes[HDIM];
    const int b    = blockIdx.x;
    const int tid  = threadIdx.x;
    const int lane = tid & 31;
    const int wid  = tid >> 5;

    for (int j = tid; j < HDIM; j += 256) {
        qs[j]  = q[(size_t)b * HDIM + j];
        wbs[j] = Wb[j];
        bks[j] = bk[j];
        gks[j] = gk[j];
        bes[j] = betak[j];
    }
    __syncthreads();
    const float bbv = bb[0];

    for (int s = wid; s < SDIM; s += 8) {
        const size_t base = ((size_t)b * SDIM + s) * HDIM;
        float x[32];
        float sm = 0.f, sq = 0.f;
        #pragma unroll
        for (int i = 0; i < 16; i++) {
            int j = i * 64 + lane * 2;
            __nv_bfloat162 v = *(const __nv_bfloat162*)(kc + base + j);
            float a = __low2float(v)  + bks[j];
            float c = __high2float(v) + bks[j + 1];
            x[2*i] = a; x[2*i+1] = c;
            sm += a + c; sq += a * a + c * c;
        }
        #pragma unroll
        for (int o = 16; o > 0; o >>= 1) {
            sm += __shfl_xor_sync(0xffffffffu, sm, o);
            sq += __shfl_xor_sync(0xffffffffu, sq, o);
        }
        float mean = sm * (1.f / 1024.f);
        float var  = sq * (1.f / 1024.f) - mean * mean;
        float rstd = rsqrtf(var + 1e-5f);

        float acc = 0.f;
        #pragma unroll
        for (int i = 0; i < 16; i++) {
            int j = i * 64 + lane * 2;
            float kv0 = (x[2*i]   - mean) * rstd * gks[j]   + bes[j];
            float kv1 = (x[2*i+1] - mean) * rstd * gks[j+1] + bes[j+1];
            acc += fmaxf(qs[j]   + kv0, 0.f) * wbs[j];
            acc += fmaxf(qs[j+1] + kv1, 0.f) * wbs[j+1];
        }
        #pragma unroll
        for (int o = 16; o > 0; o >>= 1)
            acc += __shfl_xor_sync(0xffffffffu, acc, o);

        if (lane == 0)
            beta[(size_t)b * SDIM + s] = (acc + bbv) * (1.f / 32.f);
    }
}

// ---------------- masked softmax + cumsums ----------------
__global__ void softmax_k(const float* __restrict__ beta,
                          const float* __restrict__ prev_p,
                          float* __restrict__ out)
{
    int b = blockIdx.x * blockDim.x + threadIdx.x;
    if (b >= BDIM) return;
    const float* bt = beta   + (size_t)b * SDIM;
    const float* pp = prev_p + (size_t)b * SDIM;

    float mx = -1e30f;
    #pragma unroll
    for (int s = 0; s < SDIM; s++) mx = fmaxf(mx, bt[s]);

    float pcs[SDIM];
    float run = 0.f;
    #pragma unroll
    for (int s = 0; s < SDIM; s++) { run += pp[s]; pcs[s] = run; }

    float x[SDIM];
    float denom = 0.f;
    #pragma unroll
    for (int s = 0; s < SDIM; s++) {
        float mask = (s < SDIM - 1)
                   ? ((pcs[s + 1] < 1e-5f) ? 0.f : pcs[s + 1])
                   : 1.f;
        x[s] = expf(bt[s] - mx) * mask;
        denom += fabsf(x[s]);
    }
    denom = fmaxf(denom, 1e-12f);

    const size_t BS = (size_t)BDIM * SDIM;
    float cp = 0.f;
    #pragma unroll
    for (int s = 0; s < SDIM; s++) {
        float p = x[s] / denom;
        x[s] = p;
        cp += p;
        out[0 * BS + (size_t)b * SDIM + s] = cp;
        out[2 * BS + (size_t)b * SDIM + s] = p;
    }
    float rcp = 0.f;
    #pragma unroll
    for (int s = SDIM - 1; s >= 0; s--) {
        rcp += x[s];
        out[1 * BS + (size_t)b * SDIM + s] = rcp;
    }
}

// ---------------- launch ----------------
extern "C" void kernel_launch(void* const* d_in, const int* in_sizes, int n_in,
                              void* d_out, int out_size)
{
    const float* in_val     = (const float*)d_in[0];
    const float* prev_out_M = (const float*)d_in[1];
    const float* prev_p     = (const float*)d_in[2];
    const float* Wq         = (const float*)d_in[3];
    const float* bq         = (const float*)d_in[4];
    const float* gq         = (const float*)d_in[5];
    const float* betaq      = (const float*)d_in[6];
    const float* Wk         = (const float*)d_in[7];
    const float* bk         = (const float*)d_in[8];
    const float* gk         = (const float*)d_in[9];
    const float* betak      = (const float*)d_in[10];
    const float* Wb         = (const float*)d_in[11];
    const float* bb         = (const float*)d_in[12];
    float* out = (float*)d_out;

    __nv_bfloat16 *abf, *inbf, *wqt, *wkt, *kc, *qpre;
    float *qf, *betap;
    cudaGetSymbolAddress((void**)&abf,   g_abf);
    cudaGetSymbolAddress((void**)&inbf,  g_inbf);
    cudaGetSymbolAddress((void**)&wqt,   g_wqt);
    cudaGetSymbolAddress((void**)&wkt,   g_wkt);
    cudaGetSymbolAddress((void**)&kc,    g_kc);
    cudaGetSymbolAddress((void**)&qpre,  g_qpre);
    cudaGetSymbolAddress((void**)&qf,    g_q);
    cudaGetSymbolAddress((void**)&betap, g_beta);

    cudaFuncSetAttribute(gemm_bf16_k, cudaFuncAttributeMaxDynamicSharedMemorySize, GEMM_SMEM);

    cvt_k <<<((size_t)MROWS * HDIM / 8) / 256, 256>>>(prev_out_M, abf);
    cvt_k <<<((size_t)BDIM  * HDIM / 8) / 256, 256>>>(in_val, inbf);
    cvtT_k<<<dim3(32, 32), dim3(32, 8)>>>(Wq, wqt);
    cvtT_k<<<dim3(32, 32), dim3(32, 8)>>>(Wk, wkt);

    gemm_bf16_k<<<dim3(8, BDIM  / 128), 256, GEMM_SMEM>>>(inbf, wqt, qpre);
    gemm_bf16_k<<<dim3(8, MROWS / 128), 256, GEMM_SMEM>>>(abf,  wkt, kc);

    ln_q_k   <<<BDIM / 8, 256>>>(qpre, bq, gq, betaq, qf);
    beta_k   <<<BDIM, 256>>>(kc, qf, bk, gk, betak, Wb, bb, betap);
    softmax_k<<<(BDIM + 127) / 128, 128>>>(betap, prev_p, out);
}